// round 1
// baseline (speedup 1.0000x reference)
#include <cuda_runtime.h>
#include <cuda_bf16.h>

// Problem shape (fixed by the dataset problem)
#define BB 8
#define DD 8
#define HH 512
#define WW 1024
#define PP (HH * WW)      // 524288 pixels per image
#define KK 5              // instance labels 1..K
#define P4 (PP / 4)       // float4 groups per channel plane

#define DELTA_V 0.5f
#define TWO_DELTA_D 6.0f
#define GAMMA 0.001f

#define NBLK 37           // blocks per batch for the big passes
#define NTHR 256
#define NWARP (NTHR / 32)

// -------- scratch (device globals; no allocation allowed) --------
__device__ float g_sum[BB][KK][DD];
__device__ float g_cnt[BB][KK];
__device__ float g_center[BB][KK][DD];
__device__ float g_val[BB][KK];
__device__ float g_dist[BB];
__device__ float g_reg[BB];
__device__ float g_Ninst[BB];

__device__ __forceinline__ float warp_sum(float v) {
    #pragma unroll
    for (int o = 16; o > 0; o >>= 1)
        v += __shfl_down_sync(0xffffffffu, v, o);
    return v;
}

// -------- 0: zero accumulators (graph replays, must re-zero) --------
__global__ void k_zero() {
    int t = threadIdx.x;
    float* a = &g_sum[0][0][0];                 // BB*KK*DD = 320
    float* b = &g_cnt[0][0];                    // BB*KK = 40
    float* c = &g_val[0][0];                    // BB*KK = 40
    for (int i = t; i < BB * KK * DD; i += blockDim.x) a[i] = 0.f;
    if (t < BB * KK) { b[t] = 0.f; c[t] = 0.f; }
}

// -------- 1: per-instance sums + counts --------
__global__ __launch_bounds__(NTHR) void k_pass1(const float* __restrict__ emb,
                                                const int* __restrict__ mask) {
    const int b = blockIdx.y;
    const float4* __restrict__ e0 =
        reinterpret_cast<const float4*>(emb + (size_t)b * DD * PP);
    const int4* __restrict__ m0 =
        reinterpret_cast<const int4*>(mask + (size_t)b * PP);

    float s[KK][DD];
    float cnt[KK];
    #pragma unroll
    for (int k = 0; k < KK; k++) {
        cnt[k] = 0.f;
        #pragma unroll
        for (int d = 0; d < DD; d++) s[k][d] = 0.f;
    }

    const int stride = gridDim.x * blockDim.x;
    for (int i = blockIdx.x * blockDim.x + threadIdx.x; i < P4; i += stride) {
        int4 lab4 = m0[i];
        float ev[4][DD];
        #pragma unroll
        for (int d = 0; d < DD; d++) {
            float4 v = e0[(size_t)d * P4 + i];
            ev[0][d] = v.x; ev[1][d] = v.y; ev[2][d] = v.z; ev[3][d] = v.w;
        }
        int labs[4] = {lab4.x, lab4.y, lab4.z, lab4.w};
        #pragma unroll
        for (int j = 0; j < 4; j++) {
            int lab = labs[j];
            #pragma unroll
            for (int k = 0; k < KK; k++) {
                if (lab == k + 1) {
                    cnt[k] += 1.f;
                    #pragma unroll
                    for (int d = 0; d < DD; d++) s[k][d] += ev[j][d];
                }
            }
        }
    }

    // warp tree-reduce all 45 accumulators
    #pragma unroll
    for (int k = 0; k < KK; k++) {
        cnt[k] = warp_sum(cnt[k]);
        #pragma unroll
        for (int d = 0; d < DD; d++) s[k][d] = warp_sum(s[k][d]);
    }

    __shared__ float red[NWARP][KK * DD + KK];
    int w = threadIdx.x >> 5, lane = threadIdx.x & 31;
    if (lane == 0) {
        #pragma unroll
        for (int k = 0; k < KK; k++) {
            #pragma unroll
            for (int d = 0; d < DD; d++) red[w][k * DD + d] = s[k][d];
            red[w][KK * DD + k] = cnt[k];
        }
    }
    __syncthreads();
    int t = threadIdx.x;
    if (t < KK * DD) {
        float tot = 0.f;
        #pragma unroll
        for (int ww = 0; ww < NWARP; ww++) tot += red[ww][t];
        atomicAdd(&g_sum[b][0][0] + t, tot);
    } else if (t < KK * DD + KK) {
        float tot = 0.f;
        #pragma unroll
        for (int ww = 0; ww < NWARP; ww++) tot += red[ww][t];
        atomicAdd(&g_cnt[b][t - KK * DD], tot);
    }
}

// -------- 2: centers + dist/reg losses (tiny) --------
__global__ void k_centers() {
    int t = threadIdx.x;
    for (int i = t; i < BB * KK * DD; i += blockDim.x) {
        int b = i / (KK * DD), r = i % (KK * DD), k = r / DD, d = r % DD;
        g_center[b][k][d] = g_sum[b][k][d] / fmaxf(g_cnt[b][k], 1.f);
    }
    __syncthreads();
    if (t < BB) {
        int b = t;
        float cc[KK][DD];
        bool pres[KK];
        float Nf = 0.f;
        #pragma unroll
        for (int k = 0; k < KK; k++) {
            pres[k] = g_cnt[b][k] > 0.f;
            if (pres[k]) Nf += 1.f;
            #pragma unroll
            for (int d = 0; d < DD; d++) cc[k][d] = g_center[b][k][d];
        }
        // pairwise center hinge
        float dist = 0.f;
        #pragma unroll
        for (int i = 0; i < KK; i++) {
            #pragma unroll
            for (int j = i + 1; j < KK; j++) {
                if (pres[i] && pres[j]) {
                    float ds = 0.f;
                    #pragma unroll
                    for (int d = 0; d < DD; d++) {
                        float df = cc[i][d] - cc[j][d];
                        ds += df * df;
                    }
                    float h = fmaxf(TWO_DELTA_D - sqrtf(ds), 0.f);
                    dist += h * h;
                }
            }
        }
        float npairs = Nf * (Nf - 1.f) * 0.5f;
        g_dist[b] = dist / (Nf > 1.f ? npairs : 1.f);
        // reg
        float reg = 0.f;
        #pragma unroll
        for (int k = 0; k < KK; k++) {
            if (pres[k]) {
                float n2 = 0.f;
                #pragma unroll
                for (int d = 0; d < DD; d++) n2 += cc[k][d] * cc[k][d];
                reg += sqrtf(n2);
            }
        }
        g_reg[b] = reg / fmaxf(Nf, 1.f);
        g_Ninst[b] = Nf;
    }
}

// -------- 3: variance pass --------
__global__ __launch_bounds__(NTHR) void k_pass2(const float* __restrict__ emb,
                                                const int* __restrict__ mask) {
    const int b = blockIdx.y;
    __shared__ float sc[KK][DD];
    if (threadIdx.x < KK * DD)
        sc[threadIdx.x / DD][threadIdx.x % DD] =
            g_center[b][threadIdx.x / DD][threadIdx.x % DD];
    __syncthreads();

    const float4* __restrict__ e0 =
        reinterpret_cast<const float4*>(emb + (size_t)b * DD * PP);
    const int4* __restrict__ m0 =
        reinterpret_cast<const int4*>(mask + (size_t)b * PP);

    float val[KK];
    #pragma unroll
    for (int k = 0; k < KK; k++) val[k] = 0.f;

    const int stride = gridDim.x * blockDim.x;
    for (int i = blockIdx.x * blockDim.x + threadIdx.x; i < P4; i += stride) {
        int4 lab4 = m0[i];
        float ev[4][DD];
        #pragma unroll
        for (int d = 0; d < DD; d++) {
            float4 v = e0[(size_t)d * P4 + i];
            ev[0][d] = v.x; ev[1][d] = v.y; ev[2][d] = v.z; ev[3][d] = v.w;
        }
        int labs[4] = {lab4.x, lab4.y, lab4.z, lab4.w};
        #pragma unroll
        for (int j = 0; j < 4; j++) {
            int lab = labs[j];
            if (lab > 0) {
                int kidx = lab - 1;
                float d2 = 0.f;
                #pragma unroll
                for (int d = 0; d < DD; d++) {
                    float df = ev[j][d] - sc[kidx][d];
                    d2 += df * df;
                }
                float h = fmaxf(sqrtf(d2) - DELTA_V, 0.f);
                float v = h * h;
                #pragma unroll
                for (int k = 0; k < KK; k++)
                    if (kidx == k) val[k] += v;
            }
        }
    }

    #pragma unroll
    for (int k = 0; k < KK; k++) val[k] = warp_sum(val[k]);

    __shared__ float red[NWARP][KK];
    int w = threadIdx.x >> 5, lane = threadIdx.x & 31;
    if (lane == 0) {
        #pragma unroll
        for (int k = 0; k < KK; k++) red[w][k] = val[k];
    }
    __syncthreads();
    if (threadIdx.x < KK) {
        float tot = 0.f;
        #pragma unroll
        for (int ww = 0; ww < NWARP; ww++) tot += red[ww][threadIdx.x];
        atomicAdd(&g_val[b][threadIdx.x], tot);
    }
}

// -------- 4: finalize --------
__global__ void k_final(float* __restrict__ out, int out_size) {
    if (threadIdx.x == 0) {
        float lv = 0.f, ld = 0.f, lr = 0.f, den = 0.f;
        for (int b = 0; b < BB; b++) {
            float Nf = g_Ninst[b];
            float var_b = 0.f;
            #pragma unroll
            for (int k = 0; k < KK; k++) {
                float c = g_cnt[b][k];
                if (c > 0.f) var_b += g_val[b][k] / c;
            }
            var_b /= fmaxf(Nf, 1.f);
            float has = (Nf > 0.f) ? 1.f : 0.f;
            lv += var_b * has;
            ld += g_dist[b] * has;
            lr += g_reg[b] * has;
            den += has;
        }
        den = fmaxf(den, 1.f);
        lv /= den; ld /= den; lr /= den;
        float total = lv + ld + GAMMA * lr;
        if (out_size > 0) out[0] = total;
        if (out_size > 1) out[1] = lv;
        if (out_size > 2) out[2] = ld;
        if (out_size > 3) out[3] = lr;
    }
    // fill any extra poisoned slots deterministically
    for (int i = 4 + (int)threadIdx.x; i < out_size; i += blockDim.x) out[i] = 0.f;
}

extern "C" void kernel_launch(void* const* d_in, const int* in_sizes, int n_in,
                              void* d_out, int out_size) {
    const float* emb = (const float*)d_in[0];
    const int* mask = (const int*)d_in[1];
    float* out = (float*)d_out;
    (void)in_sizes; (void)n_in;

    dim3 grid(NBLK, BB);
    k_zero<<<1, 256>>>();
    k_pass1<<<grid, NTHR>>>(emb, mask);
    k_centers<<<1, 256>>>();
    k_pass2<<<grid, NTHR>>>(emb, mask);
    k_final<<<1, 64>>>(out, out_size);
}

// round 3
// speedup vs baseline: 1.0485x; 1.0485x over previous
#include <cuda_runtime.h>
#include <cuda_bf16.h>

// Problem shape (fixed by the dataset problem)
#define BB 8
#define DD 8
#define HH 512
#define WW 1024
#define PP (HH * WW)      // 524288 pixels per image
#define KK 5              // instance labels 1..K
#define P4 (PP / 4)       // float4 groups per channel plane

#define DELTA_V 0.5f
#define TWO_DELTA_D 6.0f
#define GAMMA 0.001f

#define NBLK 74           // blocks per batch -> 592 CTAs = 4 CTAs/SM on 148 SMs
#define NTHR 256
#define NWARP (NTHR / 32)

// -------- scratch (device globals; no allocation allowed) --------
__device__ float g_sum[BB][KK][DD];
__device__ float g_cnt[BB][KK];
__device__ float g_center[BB][KK][DD];
__device__ float g_val[BB][KK];
__device__ float g_dist[BB];
__device__ float g_reg[BB];
__device__ float g_Ninst[BB];

__device__ __forceinline__ float warp_sum(float v) {
    #pragma unroll
    for (int o = 16; o > 0; o >>= 1)
        v += __shfl_down_sync(0xffffffffu, v, o);
    return v;
}

// -------- 0: zero accumulators (graph replays, must re-zero) --------
__global__ void k_zero() {
    int t = threadIdx.x;
    float* a = &g_sum[0][0][0];                 // BB*KK*DD = 320
    float* b = &g_cnt[0][0];                    // BB*KK = 40
    float* c = &g_val[0][0];                    // BB*KK = 40
    for (int i = t; i < BB * KK * DD; i += blockDim.x) a[i] = 0.f;
    if (t < BB * KK) { b[t] = 0.f; c[t] = 0.f; }
}

// -------- 1: per-instance sums + counts --------
__global__ __launch_bounds__(NTHR, 4) void k_pass1(const float* __restrict__ emb,
                                                   const int* __restrict__ mask) {
    const int b = blockIdx.y;
    const float4* __restrict__ e0 =
        reinterpret_cast<const float4*>(emb + (size_t)b * DD * PP);
    const int4* __restrict__ m0 =
        reinterpret_cast<const int4*>(mask + (size_t)b * PP);

    float s[KK][DD];
    float cnt[KK];
    #pragma unroll
    for (int k = 0; k < KK; k++) {
        cnt[k] = 0.f;
        #pragma unroll
        for (int d = 0; d < DD; d++) s[k][d] = 0.f;
    }

    const int stride = gridDim.x * blockDim.x;
    for (int i = blockIdx.x * blockDim.x + threadIdx.x; i < P4; i += stride) {
        int4 lab4 = m0[i];
        float ev[4][DD];
        #pragma unroll
        for (int d = 0; d < DD; d++) {
            float4 v = e0[(size_t)d * P4 + i];
            ev[0][d] = v.x; ev[1][d] = v.y; ev[2][d] = v.z; ev[3][d] = v.w;
        }
        #pragma unroll
        for (int j = 0; j < 4; j++) {
            int lab = (j == 0) ? lab4.x : (j == 1) ? lab4.y : (j == 2) ? lab4.z : lab4.w;
            #pragma unroll
            for (int k = 0; k < KK; k++) {
                bool hit = (lab == k + 1);
                cnt[k] += hit ? 1.f : 0.f;
                #pragma unroll
                for (int d = 0; d < DD; d++) s[k][d] += hit ? ev[j][d] : 0.f;
            }
        }
    }

    // warp tree-reduce all 45 accumulators
    #pragma unroll
    for (int k = 0; k < KK; k++) {
        cnt[k] = warp_sum(cnt[k]);
        #pragma unroll
        for (int d = 0; d < DD; d++) s[k][d] = warp_sum(s[k][d]);
    }

    __shared__ float red[NWARP][KK * DD + KK];
    int w = threadIdx.x >> 5, lane = threadIdx.x & 31;
    if (lane == 0) {
        #pragma unroll
        for (int k = 0; k < KK; k++) {
            #pragma unroll
            for (int d = 0; d < DD; d++) red[w][k * DD + d] = s[k][d];
            red[w][KK * DD + k] = cnt[k];
        }
    }
    __syncthreads();
    int t = threadIdx.x;
    if (t < KK * DD) {
        float tot = 0.f;
        #pragma unroll
        for (int ww = 0; ww < NWARP; ww++) tot += red[ww][t];
        atomicAdd(&g_sum[b][0][0] + t, tot);
    } else if (t < KK * DD + KK) {
        float tot = 0.f;
        #pragma unroll
        for (int ww = 0; ww < NWARP; ww++) tot += red[ww][t];
        atomicAdd(&g_cnt[b][t - KK * DD], tot);
    }
}

// -------- 2: centers + dist/reg losses (tiny) --------
__global__ void k_centers() {
    int t = threadIdx.x;
    for (int i = t; i < BB * KK * DD; i += blockDim.x) {
        int b = i / (KK * DD), r = i % (KK * DD), k = r / DD, d = r % DD;
        g_center[b][k][d] = g_sum[b][k][d] / fmaxf(g_cnt[b][k], 1.f);
    }
    __syncthreads();
    if (t < BB) {
        int b = t;
        float cc[KK][DD];
        bool pres[KK];
        float Nf = 0.f;
        #pragma unroll
        for (int k = 0; k < KK; k++) {
            pres[k] = g_cnt[b][k] > 0.f;
            if (pres[k]) Nf += 1.f;
            #pragma unroll
            for (int d = 0; d < DD; d++) cc[k][d] = g_center[b][k][d];
        }
        // pairwise center hinge
        float dist = 0.f;
        #pragma unroll
        for (int i = 0; i < KK; i++) {
            #pragma unroll
            for (int j = i + 1; j < KK; j++) {
                if (pres[i] && pres[j]) {
                    float ds = 0.f;
                    #pragma unroll
                    for (int d = 0; d < DD; d++) {
                        float df = cc[i][d] - cc[j][d];
                        ds += df * df;
                    }
                    float h = fmaxf(TWO_DELTA_D - sqrtf(ds), 0.f);
                    dist += h * h;
                }
            }
        }
        float npairs = Nf * (Nf - 1.f) * 0.5f;
        g_dist[b] = dist / (Nf > 1.f ? npairs : 1.f);
        // reg
        float reg = 0.f;
        #pragma unroll
        for (int k = 0; k < KK; k++) {
            if (pres[k]) {
                float n2 = 0.f;
                #pragma unroll
                for (int d = 0; d < DD; d++) n2 += cc[k][d] * cc[k][d];
                reg += sqrtf(n2);
            }
        }
        g_reg[b] = reg / fmaxf(Nf, 1.f);
        g_Ninst[b] = Nf;
    }
}

// -------- 3: variance pass --------
__global__ __launch_bounds__(NTHR, 4) void k_pass2(const float* __restrict__ emb,
                                                   const int* __restrict__ mask) {
    const int b = blockIdx.y;
    __shared__ float sc[KK][DD];
    if (threadIdx.x < KK * DD)
        sc[threadIdx.x / DD][threadIdx.x % DD] =
            g_center[b][threadIdx.x / DD][threadIdx.x % DD];
    __syncthreads();

    const float4* __restrict__ e0 =
        reinterpret_cast<const float4*>(emb + (size_t)b * DD * PP);
    const int4* __restrict__ m0 =
        reinterpret_cast<const int4*>(mask + (size_t)b * PP);

    float val[KK];
    #pragma unroll
    for (int k = 0; k < KK; k++) val[k] = 0.f;

    const int stride = gridDim.x * blockDim.x;
    for (int i = blockIdx.x * blockDim.x + threadIdx.x; i < P4; i += stride) {
        int4 lab4 = m0[i];
        float ev[4][DD];
        #pragma unroll
        for (int d = 0; d < DD; d++) {
            float4 v = e0[(size_t)d * P4 + i];
            ev[0][d] = v.x; ev[1][d] = v.y; ev[2][d] = v.z; ev[3][d] = v.w;
        }
        #pragma unroll
        for (int j = 0; j < 4; j++) {
            int lab = (j == 0) ? lab4.x : (j == 1) ? lab4.y : (j == 2) ? lab4.z : lab4.w;
            if (lab > 0) {
                int kidx = lab - 1;
                float d2 = 0.f;
                #pragma unroll
                for (int d = 0; d < DD; d++) {
                    float df = ev[j][d] - sc[kidx][d];
                    d2 += df * df;
                }
                float h = fmaxf(sqrtf(d2) - DELTA_V, 0.f);
                float v = h * h;
                #pragma unroll
                for (int k = 0; k < KK; k++)
                    if (kidx == k) val[k] += v;
            }
        }
    }

    #pragma unroll
    for (int k = 0; k < KK; k++) val[k] = warp_sum(val[k]);

    __shared__ float red[NWARP][KK];
    int w = threadIdx.x >> 5, lane = threadIdx.x & 31;
    if (lane == 0) {
        #pragma unroll
        for (int k = 0; k < KK; k++) red[w][k] = val[k];
    }
    __syncthreads();
    if (threadIdx.x < KK) {
        float tot = 0.f;
        #pragma unroll
        for (int ww = 0; ww < NWARP; ww++) tot += red[ww][threadIdx.x];
        atomicAdd(&g_val[b][threadIdx.x], tot);
    }
}

// -------- 4: finalize --------
__global__ void k_final(float* __restrict__ out, int out_size) {
    if (threadIdx.x == 0) {
        float lv = 0.f, ld = 0.f, lr = 0.f, den = 0.f;
        for (int b = 0; b < BB; b++) {
            float Nf = g_Ninst[b];
            float var_b = 0.f;
            #pragma unroll
            for (int k = 0; k < KK; k++) {
                float c = g_cnt[b][k];
                if (c > 0.f) var_b += g_val[b][k] / c;
            }
            var_b /= fmaxf(Nf, 1.f);
            float has = (Nf > 0.f) ? 1.f : 0.f;
            lv += var_b * has;
            ld += g_dist[b] * has;
            lr += g_reg[b] * has;
            den += has;
        }
        den = fmaxf(den, 1.f);
        lv /= den; ld /= den; lr /= den;
        float total = lv + ld + GAMMA * lr;
        if (out_size > 0) out[0] = total;
        if (out_size > 1) out[1] = lv;
        if (out_size > 2) out[2] = ld;
        if (out_size > 3) out[3] = lr;
    }
    // fill any extra poisoned slots deterministically
    for (int i = 4 + (int)threadIdx.x; i < out_size; i += blockDim.x) out[i] = 0.f;
}

extern "C" void kernel_launch(void* const* d_in, const int* in_sizes, int n_in,
                              void* d_out, int out_size) {
    const float* emb = (const float*)d_in[0];
    const int* mask = (const int*)d_in[1];
    float* out = (float*)d_out;
    (void)in_sizes; (void)n_in;

    dim3 grid(NBLK, BB);
    k_zero<<<1, 256>>>();
    k_pass1<<<grid, NTHR>>>(emb, mask);
    k_centers<<<1, 256>>>();
    k_pass2<<<grid, NTHR>>>(emb, mask);
    k_final<<<1, 64>>>(out, out_size);
}

// round 4
// speedup vs baseline: 1.1927x; 1.1375x over previous
#include <cuda_runtime.h>
#include <cuda_bf16.h>

// Problem shape (fixed by the dataset problem)
#define BB 8
#define DD 8
#define HH 512
#define WW 1024
#define PP (HH * WW)      // 524288 pixels per image
#define KK 5              // instance labels 1..K
#define P2 (PP / 2)       // float2 groups per channel plane

#define DELTA_V 0.5f
#define TWO_DELTA_D 6.0f
#define GAMMA 0.001f

#define NBLK1 74          // pass1 blocks/batch: 592 CTAs = 4/SM @ 64 regs
#define NBLK2 92          // pass2 blocks/batch: 736 CTAs = 5/SM @ 51 regs
#define NTHR 256
#define NWARP (NTHR / 32)

// -------- scratch (device globals; zero-initialized at module load,
// re-zeroed by k_final so every graph replay sees clean state) --------
__device__ float g_sum[BB][KK][DD];
__device__ float g_cnt[BB][KK];
__device__ float g_val[BB][KK];

__device__ __forceinline__ float warp_sum(float v) {
    #pragma unroll
    for (int o = 16; o > 0; o >>= 1)
        v += __shfl_down_sync(0xffffffffu, v, o);
    return v;
}

// ============ pass 1: per-instance sums + counts ============
// float2 path, no transpose buffer -> live regs ~55, no spill at 64-reg cap.
__global__ __launch_bounds__(NTHR, 4) void k_pass1(const float* __restrict__ emb,
                                                   const int* __restrict__ mask) {
    const int b = blockIdx.y;
    const float2* __restrict__ e0 =
        reinterpret_cast<const float2*>(emb + (size_t)b * DD * PP);
    const int2* __restrict__ m0 =
        reinterpret_cast<const int2*>(mask + (size_t)b * PP);

    float s[KK][DD];
    float cnt[KK];
    #pragma unroll
    for (int k = 0; k < KK; k++) {
        cnt[k] = 0.f;
        #pragma unroll
        for (int d = 0; d < DD; d++) s[k][d] = 0.f;
    }

    const int stride = gridDim.x * blockDim.x;
    for (int i = blockIdx.x * blockDim.x + threadIdx.x; i < P2; i += stride) {
        int2 l2 = m0[i];
        int la = l2.x, lb = l2.y;
        #pragma unroll
        for (int k = 0; k < KK; k++) {
            cnt[k] += (la == k + 1) ? 1.f : 0.f;
            cnt[k] += (lb == k + 1) ? 1.f : 0.f;
        }
        #pragma unroll
        for (int d = 0; d < DD; d++) {
            float2 v = e0[(size_t)d * P2 + i];
            #pragma unroll
            for (int k = 0; k < KK; k++) {
                s[k][d] += (la == k + 1) ? v.x : 0.f;
                s[k][d] += (lb == k + 1) ? v.y : 0.f;
            }
        }
    }

    // warp tree-reduce all 45 accumulators
    #pragma unroll
    for (int k = 0; k < KK; k++) {
        cnt[k] = warp_sum(cnt[k]);
        #pragma unroll
        for (int d = 0; d < DD; d++) s[k][d] = warp_sum(s[k][d]);
    }

    __shared__ float red[NWARP][KK * DD + KK];
    int w = threadIdx.x >> 5, lane = threadIdx.x & 31;
    if (lane == 0) {
        #pragma unroll
        for (int k = 0; k < KK; k++) {
            #pragma unroll
            for (int d = 0; d < DD; d++) red[w][k * DD + d] = s[k][d];
            red[w][KK * DD + k] = cnt[k];
        }
    }
    __syncthreads();
    int t = threadIdx.x;
    if (t < KK * DD) {
        float tot = 0.f;
        #pragma unroll
        for (int ww = 0; ww < NWARP; ww++) tot += red[ww][t];
        atomicAdd(&g_sum[b][0][0] + t, tot);
    } else if (t < KK * DD + KK) {
        float tot = 0.f;
        #pragma unroll
        for (int ww = 0; ww < NWARP; ww++) tot += red[ww][t];
        atomicAdd(&g_cnt[b][t - KK * DD], tot);
    }
}

// ============ pass 2: variance hinge ============
// Each block derives centers locally from g_sum/g_cnt (no k_centers kernel).
__global__ __launch_bounds__(NTHR, 5) void k_pass2(const float* __restrict__ emb,
                                                   const int* __restrict__ mask) {
    const int b = blockIdx.y;
    __shared__ float sc[KK * DD];   // center rows, 32B apart -> LDS128-friendly
    if (threadIdx.x < KK * DD) {
        int k = threadIdx.x / DD, d = threadIdx.x % DD;
        sc[threadIdx.x] = g_sum[b][k][d] / fmaxf(g_cnt[b][k], 1.f);
    }
    __syncthreads();

    const float2* __restrict__ e0 =
        reinterpret_cast<const float2*>(emb + (size_t)b * DD * PP);
    const int2* __restrict__ m0 =
        reinterpret_cast<const int2*>(mask + (size_t)b * PP);

    float val[KK];
    #pragma unroll
    for (int k = 0; k < KK; k++) val[k] = 0.f;

    const int stride = gridDim.x * blockDim.x;
    for (int i = blockIdx.x * blockDim.x + threadIdx.x; i < P2; i += stride) {
        int2 l2 = m0[i];
        float ea[DD], eb[DD];
        #pragma unroll
        for (int d = 0; d < DD; d++) {
            float2 v = e0[(size_t)d * P2 + i];
            ea[d] = v.x; eb[d] = v.y;
        }
        #pragma unroll
        for (int j = 0; j < 2; j++) {
            int lab = (j == 0) ? l2.x : l2.y;
            const float* e = (j == 0) ? ea : eb;
            if (lab > 0) {
                int kidx = lab - 1;
                const float4* crow = reinterpret_cast<const float4*>(&sc[kidx * DD]);
                float4 c0 = crow[0];
                float4 c1 = crow[1];
                float d2 = 0.f;
                float df;
                df = e[0] - c0.x; d2 += df * df;
                df = e[1] - c0.y; d2 += df * df;
                df = e[2] - c0.z; d2 += df * df;
                df = e[3] - c0.w; d2 += df * df;
                df = e[4] - c1.x; d2 += df * df;
                df = e[5] - c1.y; d2 += df * df;
                df = e[6] - c1.z; d2 += df * df;
                df = e[7] - c1.w; d2 += df * df;
                float h = fmaxf(sqrtf(d2) - DELTA_V, 0.f);
                float v = h * h;
                #pragma unroll
                for (int k = 0; k < KK; k++)
                    val[k] += (kidx == k) ? v : 0.f;
            }
        }
    }

    #pragma unroll
    for (int k = 0; k < KK; k++) val[k] = warp_sum(val[k]);

    __shared__ float red[NWARP][KK];
    int w = threadIdx.x >> 5, lane = threadIdx.x & 31;
    if (lane == 0) {
        #pragma unroll
        for (int k = 0; k < KK; k++) red[w][k] = val[k];
    }
    __syncthreads();
    if (threadIdx.x < KK) {
        float tot = 0.f;
        #pragma unroll
        for (int ww = 0; ww < NWARP; ww++) tot += red[ww][threadIdx.x];
        atomicAdd(&g_val[b][threadIdx.x], tot);
    }
}

// ============ finalize: dist/reg losses, batch means, re-zero scratch ============
__global__ void k_final(float* __restrict__ out, int out_size) {
    __shared__ float sh_v[BB], sh_d[BB], sh_r[BB], sh_n[BB];
    int t = threadIdx.x;
    if (t < BB) {
        int b = t;
        float cc[KK][DD];
        bool pres[KK];
        float Nf = 0.f;
        float var_b = 0.f;
        #pragma unroll
        for (int k = 0; k < KK; k++) {
            float c = g_cnt[b][k];
            pres[k] = c > 0.f;
            if (pres[k]) { Nf += 1.f; var_b += g_val[b][k] / c; }
            float inv = 1.f / fmaxf(c, 1.f);
            #pragma unroll
            for (int d = 0; d < DD; d++) cc[k][d] = g_sum[b][k][d] * inv;
        }
        var_b /= fmaxf(Nf, 1.f);
        // pairwise center hinge
        float dist = 0.f;
        #pragma unroll
        for (int i = 0; i < KK; i++) {
            #pragma unroll
            for (int j = i + 1; j < KK; j++) {
                if (pres[i] && pres[j]) {
                    float ds = 0.f;
                    #pragma unroll
                    for (int d = 0; d < DD; d++) {
                        float df = cc[i][d] - cc[j][d];
                        ds += df * df;
                    }
                    float h = fmaxf(TWO_DELTA_D - sqrtf(ds), 0.f);
                    dist += h * h;
                }
            }
        }
        float npairs = Nf * (Nf - 1.f) * 0.5f;
        dist /= (Nf > 1.f) ? npairs : 1.f;
        // reg
        float reg = 0.f;
        #pragma unroll
        for (int k = 0; k < KK; k++) {
            if (pres[k]) {
                float n2 = 0.f;
                #pragma unroll
                for (int d = 0; d < DD; d++) n2 += cc[k][d] * cc[k][d];
                reg += sqrtf(n2);
            }
        }
        reg /= fmaxf(Nf, 1.f);
        sh_v[b] = var_b; sh_d[b] = dist; sh_r[b] = reg; sh_n[b] = Nf;
    }
    __syncthreads();
    if (t == 0) {
        float lv = 0.f, ld = 0.f, lr = 0.f, den = 0.f;
        #pragma unroll
        for (int b = 0; b < BB; b++) {
            float has = (sh_n[b] > 0.f) ? 1.f : 0.f;
            lv += sh_v[b] * has;
            ld += sh_d[b] * has;
            lr += sh_r[b] * has;
            den += has;
        }
        den = fmaxf(den, 1.f);
        lv /= den; ld /= den; lr /= den;
        float total = lv + ld + GAMMA * lr;
        if (out_size > 0) out[0] = total;
        if (out_size > 1) out[1] = lv;
        if (out_size > 2) out[2] = ld;
        if (out_size > 3) out[3] = lr;
    }
    // fill extra poisoned slots deterministically
    for (int i = 4 + t; i < out_size; i += blockDim.x) out[i] = 0.f;
    // re-zero scratch for the next graph replay (state was consumed above)
    __syncthreads();
    float* a = &g_sum[0][0][0];                 // 320
    for (int i = t; i < BB * KK * DD; i += blockDim.x) a[i] = 0.f;
    if (t < BB * KK) { (&g_cnt[0][0])[t] = 0.f; (&g_val[0][0])[t] = 0.f; }
}

extern "C" void kernel_launch(void* const* d_in, const int* in_sizes, int n_in,
                              void* d_out, int out_size) {
    const float* emb = (const float*)d_in[0];
    const int* mask = (const int*)d_in[1];
    float* out = (float*)d_out;
    (void)in_sizes; (void)n_in;

    k_pass1<<<dim3(NBLK1, BB), NTHR>>>(emb, mask);
    k_pass2<<<dim3(NBLK2, BB), NTHR>>>(emb, mask);
    k_final<<<1, 128>>>(out, out_size);
}